// round 3
// baseline (speedup 1.0000x reference)
#include <cuda_runtime.h>

#define Bq 8
#define Tq 512
#define Cq 1024
#define Hq 16
#define Eq 64
#define Lq 2048

// Scratch (device globals — no allocation allowed)
__device__ float g_q[Bq*Hq*Tq*Eq];   // (b,h,t,e)
__device__ float g_k[Bq*Hq*Tq*Eq];
__device__ float g_v[Bq*Hq*Tq*Eq];
__device__ float g_y[Bq*Tq*Cq];      // attention output, (b,t,c)

// ---------------------------------------------------------------------------
// GEMM: out(M x N) = A(M x 1024) @ W(1024 x N) + bias
// Block tile 128x64, 256 threads, 8x4 micro-tile.
// MODE 0: A = x, scatter into g_q/g_k/g_v head layout.
// MODE 1: A = g_y, write to out (d_out).
// ---------------------------------------------------------------------------
template<int NDIM, int MODE>
__global__ __launch_bounds__(256)
void gemm_kernel(const float* __restrict__ Ain,
                 const float* __restrict__ W,
                 const float* __restrict__ bias,
                 float* __restrict__ out)
{
    const int KDIM = 1024;
    __shared__ float As[16][132];   // [k][m], padded
    __shared__ float Bs[16][68];    // [k][n], padded

    const int t  = threadIdx.x;
    const int m0 = blockIdx.y * 128;
    const int n0 = blockIdx.x * 64;
    const float* A = (MODE == 0) ? Ain : g_y;

    const int tn = t & 15;      // n quad: cols 4*tn..4*tn+3
    const int tm = t >> 4;      // m oct : rows 8*tm..8*tm+7

    float acc[8][4];
#pragma unroll
    for (int i = 0; i < 8; i++)
#pragma unroll
        for (int j = 0; j < 4; j++) acc[i][j] = 0.f;

    const int lkb = t >> 4;            // B-tile row
    const int lnv = (t & 15) * 4;      // B-tile col (float4)

    for (int k0 = 0; k0 < KDIM; k0 += 16) {
        // A tile: 128x16, transposed into As[k][m]; 2 float4 per thread
#pragma unroll
        for (int it = 0; it < 2; it++) {
            int idx = t + it * 256;
            int m   = idx >> 2;
            int kv  = (idx & 3) * 4;
            float4 a = *(const float4*)(A + (size_t)(m0 + m) * KDIM + k0 + kv);
            As[kv+0][m] = a.x; As[kv+1][m] = a.y;
            As[kv+2][m] = a.z; As[kv+3][m] = a.w;
        }
        // B tile: 16x64, direct; 1 float4 per thread
        *(float4*)&Bs[lkb][lnv] =
            *(const float4*)(W + (size_t)(k0 + lkb) * NDIM + n0 + lnv);
        __syncthreads();

#pragma unroll
        for (int k = 0; k < 16; k++) {
            float4 b4 = *(float4*)&Bs[k][tn*4];
            float4 a0 = *(float4*)&As[k][tm*8];
            float4 a1 = *(float4*)&As[k][tm*8+4];
            float av[8] = {a0.x,a0.y,a0.z,a0.w,a1.x,a1.y,a1.z,a1.w};
            float bv[4] = {b4.x,b4.y,b4.z,b4.w};
#pragma unroll
            for (int i = 0; i < 8; i++)
#pragma unroll
                for (int j = 0; j < 4; j++)
                    acc[i][j] += av[i] * bv[j];
        }
        __syncthreads();
    }

    float4 bb = *(const float4*)(bias + n0 + tn*4);

    if (MODE == 0) {
        // n0 is 64-aligned -> whole block lands in one (third, head)
        const int third = n0 / Cq;
        const int h     = (n0 % Cq) / Eq;
        float* dst = (third == 0) ? g_q : (third == 1) ? g_k : g_v;
#pragma unroll
        for (int i = 0; i < 8; i++) {
            int m  = m0 + tm*8 + i;
            int b_ = m >> 9;          // /512
            int tt = m & 511;
            float4 r = make_float4(acc[i][0]+bb.x, acc[i][1]+bb.y,
                                   acc[i][2]+bb.z, acc[i][3]+bb.w);
            *(float4*)&dst[(((size_t)(b_*Hq + h)*Tq + tt)*Eq) + tn*4] = r;
        }
    } else {
#pragma unroll
        for (int i = 0; i < 8; i++) {
            int m = m0 + tm*8 + i;
            float4 r = make_float4(acc[i][0]+bb.x, acc[i][1]+bb.y,
                                   acc[i][2]+bb.z, acc[i][3]+bb.w);
            *(float4*)&out[(size_t)m*NDIM + n0 + tn*4] = r;
        }
    }
}

// ---------------------------------------------------------------------------
// Flash attention, fp32. Block = 64-query tile for one (b,h); 256 threads.
// Thread (tn = t&15, ty = t>>4) owns rows 4*ty..+3, cols 4*tn..+3.
// QsT/KsT stored [e][row] so both GEMMs are outer-product (conflict-free).
// Softmax stats reduced with shfl over the 16-lane row group (half-warp).
// ---------------------------------------------------------------------------
#define ATTN_SMEM (4 * 64 * 68 * 4)   // 69632 B

__global__ __launch_bounds__(256)
void attn_kernel(const float* __restrict__ kc, const float* __restrict__ vc)
{
    extern __shared__ float sm[];
    float* QsT = sm;               // [e][row]  stride 68
    float* KsT = sm + 64*68;       // [e][key]
    float* Vs  = sm + 2*64*68;     // [key][e]
    float* Ps  = sm + 3*64*68;     // [row][key]

    const int qt = blockIdx.x;     // query tile (0..7)
    const int bh = blockIdx.y;     // b*16+h (0..127)
    const int t  = threadIdx.x;
    const int tn = t & 15, ty = t >> 4;
    const int keyl = t & 63, u0 = t >> 6;   // load mapping

    // Load Q tile transposed, pre-scaled by 1/sqrt(E)
    {
        const float* qp = g_q + ((size_t)bh*Tq + qt*64 + keyl)*Eq + u0*16;
#pragma unroll
        for (int u = 0; u < 4; u++) {
            float4 v = *(const float4*)(qp + 4*u);
            int e = u0*16 + 4*u;
            QsT[(e+0)*68 + keyl] = v.x * 0.125f;
            QsT[(e+1)*68 + keyl] = v.y * 0.125f;
            QsT[(e+2)*68 + keyl] = v.z * 0.125f;
            QsT[(e+3)*68 + keyl] = v.w * 0.125f;
        }
    }

    float o[4][4];
    float m_[4], l_[4];
#pragma unroll
    for (int i = 0; i < 4; i++) {
        m_[i] = -1e30f; l_[i] = 0.f;
#pragma unroll
        for (int j = 0; j < 4; j++) o[i][j] = 0.f;
    }

    const int KT = Lq/64 + qt + 1;           // 33..40 key tiles
    const float* kcb = kc + (size_t)bh*Lq*Eq;
    const float* vcb = vc + (size_t)bh*Lq*Eq;
    const float* knb = g_k + (size_t)bh*Tq*Eq;
    const float* vnb = g_v + (size_t)bh*Tq*Eq;

    for (int kt = 0; kt < KT; kt++) {
        __syncthreads();    // protect K/V/P from previous iteration readers
        {
            int j = kt*64 + keyl;
            const float* kp;
            const float* vp;
            if (j < Lq) { kp = kcb + (size_t)j*Eq; vp = vcb + (size_t)j*Eq; }
            else        { kp = knb + (size_t)(j-Lq)*Eq; vp = vnb + (size_t)(j-Lq)*Eq; }
#pragma unroll
            for (int u = 0; u < 4; u++) {
                int e = u0*16 + 4*u;
                float4 k4 = *(const float4*)(kp + e);
                KsT[(e+0)*68 + keyl] = k4.x;
                KsT[(e+1)*68 + keyl] = k4.y;
                KsT[(e+2)*68 + keyl] = k4.z;
                KsT[(e+3)*68 + keyl] = k4.w;
                *(float4*)&Vs[keyl*68 + e] = *(const float4*)(vp + e);
            }
        }
        __syncthreads();

        // ---- S = Q @ K^T (scaled) ----
        float s[4][4];
#pragma unroll
        for (int i = 0; i < 4; i++)
#pragma unroll
            for (int j = 0; j < 4; j++) s[i][j] = 0.f;

#pragma unroll 8
        for (int e = 0; e < 64; e++) {
            float4 a4 = *(float4*)&QsT[e*68 + ty*4];
            float4 b4 = *(float4*)&KsT[e*68 + tn*4];
            float av[4] = {a4.x,a4.y,a4.z,a4.w};
            float bv[4] = {b4.x,b4.y,b4.z,b4.w};
#pragma unroll
            for (int i = 0; i < 4; i++)
#pragma unroll
                for (int j = 0; j < 4; j++)
                    s[i][j] += av[i] * bv[j];
        }

        // Only the final tile is diagonal (L is tile-aligned)
        if (kt == KT-1) {
#pragma unroll
            for (int i = 0; i < 4; i++)
#pragma unroll
                for (int j = 0; j < 4; j++)
                    if (tn*4 + j > ty*4 + i) s[i][j] = -1e30f;
        }

        // ---- online softmax ----
        float mt[4];
#pragma unroll
        for (int i = 0; i < 4; i++)
            mt[i] = fmaxf(fmaxf(s[i][0], s[i][1]), fmaxf(s[i][2], s[i][3]));
#pragma unroll
        for (int off = 8; off > 0; off >>= 1)
#pragma unroll
            for (int i = 0; i < 4; i++)
                mt[i] = fmaxf(mt[i], __shfl_xor_sync(0xffffffffu, mt[i], off));

        float rs[4];
#pragma unroll
        for (int i = 0; i < 4; i++) {
            float nm   = fmaxf(m_[i], mt[i]);
            float corr = __expf(m_[i] - nm);
            m_[i] = nm;
            l_[i] *= corr;
#pragma unroll
            for (int j = 0; j < 4; j++) o[i][j] *= corr;
            float sum = 0.f;
#pragma unroll
            for (int j = 0; j < 4; j++) { s[i][j] = __expf(s[i][j] - nm); sum += s[i][j]; }
            rs[i] = sum;
        }
#pragma unroll
        for (int off = 8; off > 0; off >>= 1)
#pragma unroll
            for (int i = 0; i < 4; i++)
                rs[i] += __shfl_xor_sync(0xffffffffu, rs[i], off);
#pragma unroll
        for (int i = 0; i < 4; i++) l_[i] += rs[i];

        // ---- P to shared ----
#pragma unroll
        for (int i = 0; i < 4; i++)
            *(float4*)&Ps[(ty*4+i)*68 + tn*4] =
                make_float4(s[i][0], s[i][1], s[i][2], s[i][3]);
        __syncthreads();

        // ---- O += P @ V ----
#pragma unroll 4
        for (int kk = 0; kk < 64; kk += 4) {
            float p[4][4], v[4][4];
#pragma unroll
            for (int i = 0; i < 4; i++) {
                float4 p4 = *(float4*)&Ps[(ty*4+i)*68 + kk];
                p[i][0]=p4.x; p[i][1]=p4.y; p[i][2]=p4.z; p[i][3]=p4.w;
            }
#pragma unroll
            for (int c = 0; c < 4; c++) {
                float4 v4 = *(float4*)&Vs[(kk+c)*68 + tn*4];
                v[c][0]=v4.x; v[c][1]=v4.y; v[c][2]=v4.z; v[c][3]=v4.w;
            }
#pragma unroll
            for (int i = 0; i < 4; i++)
#pragma unroll
                for (int j = 0; j < 4; j++)
#pragma unroll
                    for (int c = 0; c < 4; c++)
                        o[i][j] += p[i][c] * v[c][j];
        }
    }

    // ---- finalize -> g_y (b,t,h*64+e) ----
    const int b_ = bh >> 4, h = bh & 15;
#pragma unroll
    for (int i = 0; i < 4; i++) {
        float inv = 1.0f / l_[i];
        int row = qt*64 + ty*4 + i;
        float4 r = make_float4(o[i][0]*inv, o[i][1]*inv, o[i][2]*inv, o[i][3]*inv);
        *(float4*)&g_y[((size_t)(b_*Tq + row))*Cq + h*Eq + tn*4] = r;
    }
}

// ---------------------------------------------------------------------------
extern "C" void kernel_launch(void* const* d_in, const int* in_sizes, int n_in,
                              void* d_out, int out_size)
{
    const float* x     = (const float*)d_in[0];
    const float* kc    = (const float*)d_in[1];
    const float* vc    = (const float*)d_in[2];
    const float* Wqkv  = (const float*)d_in[3];
    const float* bqkv  = (const float*)d_in[4];
    const float* Wproj = (const float*)d_in[5];
    const float* bproj = (const float*)d_in[6];
    float* out = (float*)d_out;

    cudaFuncSetAttribute(attn_kernel,
                         cudaFuncAttributeMaxDynamicSharedMemorySize, ATTN_SMEM);

    // 1) QKV projection -> g_q/g_k/g_v
    dim3 g1(3*Cq/64, (Bq*Tq)/128);           // (48, 32)
    gemm_kernel<3*Cq, 0><<<g1, 256>>>(x, Wqkv, bqkv, nullptr);

    // 2) Attention -> g_y
    dim3 g2(Tq/64, Bq*Hq);                   // (8, 128)
    attn_kernel<<<g2, 256, ATTN_SMEM>>>(kc, vc);

    // 3) Output projection -> d_out
    dim3 g3(Cq/64, (Bq*Tq)/128);             // (16, 32)
    gemm_kernel<Cq, 1><<<g3, 256>>>(nullptr, Wproj, bproj, out);
}

// round 4
// speedup vs baseline: 2.4270x; 2.4270x over previous
#include <cuda_runtime.h>
#include <cuda_bf16.h>

#define Bq 8
#define Tq 512
#define Cq 1024
#define Hq 16
#define Eq 64
#define Lq 2048
#define Sq 2560   // L + T

// ---------------- split-bf16 scratch (device globals) ----------------
__device__ __align__(16) __nv_bfloat16 g_xh[4096*1024], g_xl[4096*1024];
__device__ __align__(16) __nv_bfloat16 g_wqh[3072*1024], g_wql[3072*1024];  // Wqkv^T (n,k)
__device__ __align__(16) __nv_bfloat16 g_wph[1024*1024], g_wpl[1024*1024];  // Wproj^T
__device__ __align__(16) __nv_bfloat16 g_qh[Bq*Hq*Tq*Eq], g_ql[Bq*Hq*Tq*Eq];
__device__ __align__(16) __nv_bfloat16 g_kh[Bq*Hq*Sq*Eq], g_kl[Bq*Hq*Sq*Eq];
__device__ __align__(16) __nv_bfloat16 g_vh[Bq*Hq*Sq*Eq], g_vl[Bq*Hq*Sq*Eq];
__device__ __align__(16) __nv_bfloat16 g_yh[4096*1024], g_yl[4096*1024];

// ---------------- PTX helpers ----------------
__device__ __forceinline__ void mma_bf16(float* c, const unsigned* a, const unsigned* b){
    asm volatile(
        "mma.sync.aligned.m16n8k16.row.col.f32.bf16.bf16.f32 "
        "{%0,%1,%2,%3}, {%4,%5,%6,%7}, {%8,%9}, {%0,%1,%2,%3};\n"
        : "+f"(c[0]), "+f"(c[1]), "+f"(c[2]), "+f"(c[3])
        : "r"(a[0]), "r"(a[1]), "r"(a[2]), "r"(a[3]), "r"(b[0]), "r"(b[1]));
}
__device__ __forceinline__ void ldsm4(unsigned* r, unsigned addr){
    asm volatile("ldmatrix.sync.aligned.m8n8.x4.shared.b16 {%0,%1,%2,%3}, [%4];\n"
                 : "=r"(r[0]), "=r"(r[1]), "=r"(r[2]), "=r"(r[3]) : "r"(addr));
}
__device__ __forceinline__ void ldsm2(unsigned* r, unsigned addr){
    asm volatile("ldmatrix.sync.aligned.m8n8.x2.shared.b16 {%0,%1}, [%2];\n"
                 : "=r"(r[0]), "=r"(r[1]) : "r"(addr));
}
__device__ __forceinline__ void ldsm2t(unsigned* r, unsigned addr){
    asm volatile("ldmatrix.sync.aligned.m8n8.x2.trans.shared.b16 {%0,%1}, [%2];\n"
                 : "=r"(r[0]), "=r"(r[1]) : "r"(addr));
}
__device__ __forceinline__ void split_pack(float x, float y, unsigned& hi, unsigned& lo){
    __nv_bfloat16 hx = __float2bfloat16(x);
    __nv_bfloat16 hy = __float2bfloat16(y);
    __nv_bfloat16 lx = __float2bfloat16(x - __bfloat162float(hx));
    __nv_bfloat16 ly = __float2bfloat16(y - __bfloat162float(hy));
    __nv_bfloat162 H; H.x = hx; H.y = hy;
    __nv_bfloat162 Lo; Lo.x = lx; Lo.y = ly;
    hi = *reinterpret_cast<unsigned*>(&H);
    lo = *reinterpret_cast<unsigned*>(&Lo);
}
__device__ __forceinline__ void split_store(__nv_bfloat16* dh, __nv_bfloat16* dl,
                                            int idx, float x, float y){
    unsigned hi, lo; split_pack(x, y, hi, lo);
    *reinterpret_cast<unsigned*>(&dh[idx]) = hi;
    *reinterpret_cast<unsigned*>(&dl[idx]) = lo;
}

// ---------------- conversion kernels ----------------
__global__ __launch_bounds__(256) void cvt_x(const float* __restrict__ x){
    int i4 = blockIdx.x*256 + threadIdx.x;
    int base = i4*4;
    float4 v = *(const float4*)&x[base];
    split_store(g_xh, g_xl, base,   v.x, v.y);
    split_store(g_xh, g_xl, base+2, v.z, v.w);
}

// W (K=1024 rows, N cols, n-contig) -> W^T hi/lo (N rows, 1024 cols, k-contig)
__global__ __launch_bounds__(256) void cvt_wT(const float* __restrict__ W, int N, int sel){
    __shared__ float tile[32][33];
    int n0 = blockIdx.x*32, k0 = blockIdx.y*32;
    int tx = threadIdx.x & 31, ty = threadIdx.x >> 5;   // ty 0..7
    __nv_bfloat16* oh = sel ? g_wph : g_wqh;
    __nv_bfloat16* ol = sel ? g_wpl : g_wql;
#pragma unroll
    for (int i = 0; i < 4; i++)
        tile[ty + 8*i][tx] = W[(size_t)(k0 + ty + 8*i)*N + n0 + tx];
    __syncthreads();
#pragma unroll
    for (int i = 0; i < 4; i++){
        int n = n0 + ty + 8*i, k = k0 + tx;
        float v = tile[tx][ty + 8*i];
        __nv_bfloat16 h = __float2bfloat16(v);
        oh[(size_t)n*1024 + k] = h;
        ol[(size_t)n*1024 + k] = __float2bfloat16(v - __bfloat162float(h));
    }
}

__global__ __launch_bounds__(256) void cvt_kv(const float* __restrict__ kc,
                                              const float* __restrict__ vc){
    int i4 = blockIdx.x*256 + threadIdx.x;
    int base = i4*4;                       // index into (B,H,L,E)
    int bh = base >> 17;                   // /(2048*64)
    int rem = base & (Lq*Eq - 1);
    int s = rem >> 6, e = rem & 63;
    int o = (bh*Sq + s)*Eq + e;            // cache occupies s in [0,L)
    float4 k4 = *(const float4*)&kc[base];
    float4 v4 = *(const float4*)&vc[base];
    split_store(g_kh, g_kl, o,   k4.x, k4.y);
    split_store(g_kh, g_kl, o+2, k4.z, k4.w);
    split_store(g_vh, g_vl, o,   v4.x, v4.y);
    split_store(g_vh, g_vl, o+2, v4.z, v4.w);
}

// ---------------- split-bf16 MMA GEMM ----------------
// C(M x NDIM) = A(M x 1024) @ B^T, A/B stored k-contig as hi/lo bf16.
// Block 128m x 128n, 8 warps (4m x 2n), warp tile 32m x 64n.
// MODE 0: A=x, B=Wqkv^T, epilogue scatters split q/k/v (q scaled 1/8).
// MODE 1: A=y,  B=Wproj^T, epilogue writes f32 out.
template<int NDIM, int MODE>
__global__ __launch_bounds__(256) void gemm_mma(const float* __restrict__ bias,
                                               float* __restrict__ out){
    const __nv_bfloat16* Ah = MODE ? g_yh : g_xh;
    const __nv_bfloat16* Al = MODE ? g_yl : g_xl;
    const __nv_bfloat16* Bh = MODE ? g_wph : g_wqh;
    const __nv_bfloat16* Bl = MODE ? g_wpl : g_wql;

    __shared__ __align__(16) __nv_bfloat16 Ash[128*40], Asl[128*40];
    __shared__ __align__(16) __nv_bfloat16 Bsh[128*40], Bsl[128*40];

    const int t = threadIdx.x, L = t & 31, warp = t >> 5;
    const int wm = warp & 3, wn = warp >> 2;
    const int bm = blockIdx.y*128, bn = blockIdx.x*128;

    float c[2][8][4];
#pragma unroll
    for (int i=0;i<2;i++)
#pragma unroll
        for (int j=0;j<8;j++)
#pragma unroll
            for (int q=0;q<4;q++) c[i][j][q] = 0.f;

    const int lr = t >> 2, lc = t & 3;
    unsigned sAh = (unsigned)__cvta_generic_to_shared(Ash);
    unsigned sAl = (unsigned)__cvta_generic_to_shared(Asl);
    unsigned sBh = (unsigned)__cvta_generic_to_shared(Bsh);
    unsigned sBl = (unsigned)__cvta_generic_to_shared(Bsl);
    const int arow = wm*32 + (L & 15);
    const int acol = (L >> 4)*8;
    const int brow = L & 7;
    const int bcol = ((L >> 3) & 1)*8;

    for (int k0 = 0; k0 < 1024; k0 += 32){
#pragma unroll
        for (int hh = 0; hh < 2; hh++){
            int r = lr + hh*64;
            *(uint4*)&Ash[r*40 + lc*8] = *(const uint4*)&Ah[(size_t)(bm+r)*1024 + k0 + lc*8];
            *(uint4*)&Asl[r*40 + lc*8] = *(const uint4*)&Al[(size_t)(bm+r)*1024 + k0 + lc*8];
            *(uint4*)&Bsh[r*40 + lc*8] = *(const uint4*)&Bh[(size_t)(bn+r)*1024 + k0 + lc*8];
            *(uint4*)&Bsl[r*40 + lc*8] = *(const uint4*)&Bl[(size_t)(bn+r)*1024 + k0 + lc*8];
        }
        __syncthreads();
#pragma unroll
        for (int kk = 0; kk < 2; kk++){
            unsigned ah[2][4], al[2][4];
#pragma unroll
            for (int i=0;i<2;i++){
                unsigned off = (unsigned)(((arow + i*16)*40 + kk*16 + acol)*2);
                ldsm4(ah[i], sAh + off);
                ldsm4(al[i], sAl + off);
            }
#pragma unroll
            for (int j=0;j<8;j++){
                unsigned boff = (unsigned)(((wn*64 + j*8 + brow)*40 + kk*16 + bcol)*2);
                unsigned bhf[2], blf[2];
                ldsm2(bhf, sBh + boff);
                ldsm2(blf, sBl + boff);
#pragma unroll
                for (int i=0;i<2;i++){
                    mma_bf16(c[i][j], ah[i], bhf);
                    mma_bf16(c[i][j], ah[i], blf);
                    mma_bf16(c[i][j], al[i], bhf);
                }
            }
        }
        __syncthreads();
    }

    // epilogue
#pragma unroll
    for (int i=0;i<2;i++){
        int m0 = bm + wm*32 + i*16 + (L >> 2);
#pragma unroll
        for (int j=0;j<8;j++){
            int n = bn + wn*64 + j*8 + 2*(L & 3);
            float b0 = bias[n], b1 = bias[n+1];
            if (MODE == 1){
                float2 r0 = make_float2(c[i][j][0]+b0, c[i][j][1]+b1);
                float2 r1 = make_float2(c[i][j][2]+b0, c[i][j][3]+b1);
                *(float2*)&out[(size_t)m0*1024 + n] = r0;
                *(float2*)&out[(size_t)(m0+8)*1024 + n] = r1;
            } else {
                int third = n >> 10, rem = n & 1023;
                int h = rem >> 6, e = rem & 63;
                float sc = (third == 0) ? 0.125f : 1.0f;
                __nv_bfloat16* dh = (third==0) ? g_qh : (third==1) ? g_kh : g_vh;
                __nv_bfloat16* dl = (third==0) ? g_ql : (third==1) ? g_kl : g_vl;
#pragma unroll
                for (int rr = 0; rr < 2; rr++){
                    int m = m0 + rr*8;
                    int bb = m >> 9, tt = m & 511;
                    int idx = (third==0)
                        ? ((bb*Hq + h)*Tq + tt)*Eq + e
                        : ((bb*Hq + h)*Sq + Lq + tt)*Eq + e;
                    split_store(dh, dl, idx,
                                (c[i][j][2*rr]+b0)*sc, (c[i][j][2*rr+1]+b1)*sc);
                }
            }
        }
    }
}

// ---------------- flash attention with split-bf16 MMA ----------------
// Block: 128-query tile for one (b,h). 8 warps, warp w owns rows w*16..+15.
// S and P live entirely in registers (C-frag -> A-frag identity).
#define ATTN_SMEM ((128*72*2 + 64*72*4) * 2)   // 73728 B

__global__ __launch_bounds__(256) void attn_mma(){
    extern __shared__ __align__(16) __nv_bfloat16 sm[];
    __nv_bfloat16* Qh = sm;                 // 128 x 64, stride 72
    __nv_bfloat16* Ql = sm + 128*72;
    __nv_bfloat16* Kh = sm + 2*128*72;      // 64 x 64, stride 72
    __nv_bfloat16* Kl = Kh + 64*72;
    __nv_bfloat16* Vh = Kh + 2*64*72;
    __nv_bfloat16* Vl = Kh + 3*64*72;

    const int qt = blockIdx.x, bh = blockIdx.y;
    const int t = threadIdx.x, L = t & 31, w = t >> 5;

    unsigned sQh = (unsigned)__cvta_generic_to_shared(Qh);
    unsigned sQl = (unsigned)__cvta_generic_to_shared(Ql);
    unsigned sKh = (unsigned)__cvta_generic_to_shared(Kh);
    unsigned sKl = (unsigned)__cvta_generic_to_shared(Kl);
    unsigned sVh = (unsigned)__cvta_generic_to_shared(Vh);
    unsigned sVl = (unsigned)__cvta_generic_to_shared(Vl);

    // load Q tile (128 rows)
    {
        int r = t >> 1;
        int tok = qt*128 + r;
        size_t gq = ((size_t)bh*Tq + tok)*Eq;
#pragma unroll
        for (int i = 0; i < 4; i++){
            int cchunk = (t & 1)*4 + i;
            *(uint4*)&Qh[r*72 + cchunk*8] = *(const uint4*)&g_qh[gq + cchunk*8];
            *(uint4*)&Ql[r*72 + cchunk*8] = *(const uint4*)&g_ql[gq + cchunk*8];
        }
    }

    float o[8][4];
#pragma unroll
    for (int j=0;j<8;j++)
#pragma unroll
        for (int q=0;q<4;q++) o[j][q] = 0.f;
    float m0_ = -1e30f, m1_ = -1e30f, l0_ = 0.f, l1_ = 0.f;

    const int KT = 34 + 2*qt;
    const int row0 = qt*128 + w*16 + (L >> 2);   // global query row of c0/c1
    const int lim0 = Lq + row0, lim1 = lim0 + 8;

    const int ldr = t >> 2, ldc = t & 3;
    const size_t kvbase = (size_t)bh*Sq*Eq;

    for (int kt = 0; kt < KT; kt++){
        __syncthreads();
        {
            size_t gi = kvbase + (size_t)(kt*64 + ldr)*Eq;
#pragma unroll
            for (int hh = 0; hh < 2; hh++){
                int cc = ldc + hh*4;
                *(uint4*)&Kh[ldr*72 + cc*8] = *(const uint4*)&g_kh[gi + cc*8];
                *(uint4*)&Kl[ldr*72 + cc*8] = *(const uint4*)&g_kl[gi + cc*8];
                *(uint4*)&Vh[ldr*72 + cc*8] = *(const uint4*)&g_vh[gi + cc*8];
                *(uint4*)&Vl[ldr*72 + cc*8] = *(const uint4*)&g_vl[gi + cc*8];
            }
        }
        __syncthreads();

        // ---- S = Q K^T ----
        float s[8][4];
#pragma unroll
        for (int j=0;j<8;j++)
#pragma unroll
            for (int q=0;q<4;q++) s[j][q] = 0.f;

#pragma unroll
        for (int kk = 0; kk < 4; kk++){
            unsigned qa_h[4], qa_l[4];
            unsigned qoff = (unsigned)(((w*16 + (L&15))*72 + kk*16 + (L>>4)*8)*2);
            ldsm4(qa_h, sQh + qoff);
            ldsm4(qa_l, sQl + qoff);
#pragma unroll
            for (int j=0;j<8;j++){
                unsigned koff = (unsigned)(((j*8 + (L&7))*72 + kk*16 + ((L>>3)&1)*8)*2);
                unsigned kb_h[2], kb_l[2];
                ldsm2(kb_h, sKh + koff);
                ldsm2(kb_l, sKl + koff);
                mma_bf16(s[j], qa_h, kb_h);
                mma_bf16(s[j], qa_h, kb_l);
                mma_bf16(s[j], qa_l, kb_h);
            }
        }

        // ---- causal mask (only last two tiles can clip) ----
        if (kt >= KT-2){
#pragma unroll
            for (int j=0;j<8;j++){
                int col = kt*64 + j*8 + 2*(L & 3);
                if (col   > lim0) s[j][0] = -1e30f;
                if (col+1 > lim0) s[j][1] = -1e30f;
                if (col   > lim1) s[j][2] = -1e30f;
                if (col+1 > lim1) s[j][3] = -1e30f;
            }
        }

        // ---- online softmax (rows split over lane quads) ----
        float mt0 = -1e30f, mt1 = -1e30f;
#pragma unroll
        for (int j=0;j<8;j++){
            mt0 = fmaxf(mt0, fmaxf(s[j][0], s[j][1]));
            mt1 = fmaxf(mt1, fmaxf(s[j][2], s[j][3]));
        }
        mt0 = fmaxf(mt0, __shfl_xor_sync(0xffffffffu, mt0, 1));
        mt0 = fmaxf(mt0, __shfl_xor_sync(0xffffffffu, mt0, 2));
        mt1 = fmaxf(mt1, __shfl_xor_sync(0xffffffffu, mt1, 1));
        mt1 = fmaxf(mt1, __shfl_xor_sync(0xffffffffu, mt1, 2));

        float nm0 = fmaxf(m0_, mt0), nm1 = fmaxf(m1_, mt1);
        float corr0 = __expf(m0_ - nm0), corr1 = __expf(m1_ - nm1);
        m0_ = nm0; m1_ = nm1;
        l0_ *= corr0; l1_ *= corr1;
#pragma unroll
        for (int j=0;j<8;j++){
            o[j][0] *= corr0; o[j][1] *= corr0;
            o[j][2] *= corr1; o[j][3] *= corr1;
        }
        float rs0 = 0.f, rs1 = 0.f;
#pragma unroll
        for (int j=0;j<8;j++){
            s[j][0] = __expf(s[j][0] - nm0); rs0 += s[j][0];
            s[j][1] = __expf(s[j][1] - nm0); rs0 += s[j][1];
            s[j][2] = __expf(s[j][2] - nm1); rs1 += s[j][2];
            s[j][3] = __expf(s[j][3] - nm1); rs1 += s[j][3];
        }
        rs0 += __shfl_xor_sync(0xffffffffu, rs0, 1);
        rs0 += __shfl_xor_sync(0xffffffffu, rs0, 2);
        rs1 += __shfl_xor_sync(0xffffffffu, rs1, 1);
        rs1 += __shfl_xor_sync(0xffffffffu, rs1, 2);
        l0_ += rs0; l1_ += rs1;

        // ---- O += P V  (P from registers) ----
#pragma unroll
        for (int kk2 = 0; kk2 < 4; kk2++){
            unsigned pa_h[4], pa_l[4];
            split_pack(s[2*kk2][0],   s[2*kk2][1],   pa_h[0], pa_l[0]);
            split_pack(s[2*kk2][2],   s[2*kk2][3],   pa_h[1], pa_l[1]);
            split_pack(s[2*kk2+1][0], s[2*kk2+1][1], pa_h[2], pa_l[2]);
            split_pack(s[2*kk2+1][2], s[2*kk2+1][3], pa_h[3], pa_l[3]);
#pragma unroll
            for (int j=0;j<8;j++){
                unsigned voff = (unsigned)(((kk2*16 + (L&15))*72 + j*8)*2);
                unsigned vb_h[2], vb_l[2];
                ldsm2t(vb_h, sVh + voff);
                ldsm2t(vb_l, sVl + voff);
                mma_bf16(o[j], pa_h, vb_h);
                mma_bf16(o[j], pa_h, vb_l);
                mma_bf16(o[j], pa_l, vb_h);
            }
        }
    }

    // ---- finalize -> split y (b, t, h*64+e) ----
    float inv0 = 1.0f / l0_, inv1 = 1.0f / l1_;
    int b_ = bh >> 4, h = bh & 15;
    int tok0 = qt*128 + w*16 + (L >> 2);
#pragma unroll
    for (int j=0;j<8;j++){
        int cc = h*Eq + j*8 + 2*(L & 3);
        int i0 = (b_*Tq + tok0)*Cq + cc;
        int i1 = (b_*Tq + tok0 + 8)*Cq + cc;
        split_store(g_yh, g_yl, i0, o[j][0]*inv0, o[j][1]*inv0);
        split_store(g_yh, g_yl, i1, o[j][2]*inv1, o[j][3]*inv1);
    }
}

// ---------------------------------------------------------------------------
extern "C" void kernel_launch(void* const* d_in, const int* in_sizes, int n_in,
                              void* d_out, int out_size)
{
    const float* x     = (const float*)d_in[0];
    const float* kc    = (const float*)d_in[1];
    const float* vc    = (const float*)d_in[2];
    const float* Wqkv  = (const float*)d_in[3];
    const float* bqkv  = (const float*)d_in[4];
    const float* Wproj = (const float*)d_in[5];
    const float* bproj = (const float*)d_in[6];
    float* out = (float*)d_out;

    cudaFuncSetAttribute(attn_mma,
                         cudaFuncAttributeMaxDynamicSharedMemorySize, ATTN_SMEM);

    // conversions
    cvt_x<<<4096, 256>>>(x);
    cvt_wT<<<dim3(96, 32), 256>>>(Wqkv, 3072, 0);
    cvt_wT<<<dim3(32, 32), 256>>>(Wproj, 1024, 1);
    cvt_kv<<<16384, 256>>>(kc, vc);

    // QKV projection -> split q/k/v caches
    gemm_mma<3072, 0><<<dim3(24, 32), 256>>>(bqkv, nullptr);

    // attention -> split y
    attn_mma<<<dim3(4, 128), 256, ATTN_SMEM>>>();

    // output projection -> d_out (f32)
    gemm_mma<1024, 1><<<dim3(8, 32), 256>>>(bproj, out);
}

// round 6
// speedup vs baseline: 2.6528x; 1.0931x over previous
#include <cuda_runtime.h>
#include <cuda_bf16.h>
#include <cstdint>

#define Bq 8
#define Tq 512
#define Cq 1024
#define Hq 16
#define Eq 64
#define Lq 2048
#define Sq 2560   // L + T

// ---------------- split-bf16 scratch (device globals) ----------------
__device__ __align__(16) __nv_bfloat16 g_xh[4096*1024], g_xl[4096*1024];
__device__ __align__(16) __nv_bfloat16 g_wqh[3072*1024], g_wql[3072*1024];  // Wqkv^T (n,k)
__device__ __align__(16) __nv_bfloat16 g_wph[1024*1024], g_wpl[1024*1024];  // Wproj^T
__device__ __align__(16) __nv_bfloat16 g_qh[Bq*Hq*Tq*Eq], g_ql[Bq*Hq*Tq*Eq];
__device__ __align__(16) __nv_bfloat16 g_kh[Bq*Hq*Sq*Eq], g_kl[Bq*Hq*Sq*Eq];
__device__ __align__(16) __nv_bfloat16 g_vh[Bq*Hq*Sq*Eq], g_vl[Bq*Hq*Sq*Eq];
__device__ __align__(16) __nv_bfloat16 g_yh[4096*1024], g_yl[4096*1024];

// ---------------- PTX helpers ----------------
__device__ __forceinline__ void mma_bf16(float* c, const unsigned* a, const unsigned* b){
    asm volatile(
        "mma.sync.aligned.m16n8k16.row.col.f32.bf16.bf16.f32 "
        "{%0,%1,%2,%3}, {%4,%5,%6,%7}, {%8,%9}, {%0,%1,%2,%3};\n"
        : "+f"(c[0]), "+f"(c[1]), "+f"(c[2]), "+f"(c[3])
        : "r"(a[0]), "r"(a[1]), "r"(a[2]), "r"(a[3]), "r"(b[0]), "r"(b[1]));
}
__device__ __forceinline__ void ldsm4(unsigned* r, unsigned addr){
    asm volatile("ldmatrix.sync.aligned.m8n8.x4.shared.b16 {%0,%1,%2,%3}, [%4];\n"
                 : "=r"(r[0]), "=r"(r[1]), "=r"(r[2]), "=r"(r[3]) : "r"(addr));
}
__device__ __forceinline__ void ldsm2(unsigned* r, unsigned addr){
    asm volatile("ldmatrix.sync.aligned.m8n8.x2.shared.b16 {%0,%1}, [%2];\n"
                 : "=r"(r[0]), "=r"(r[1]) : "r"(addr));
}
__device__ __forceinline__ void ldsm2t(unsigned* r, unsigned addr){
    asm volatile("ldmatrix.sync.aligned.m8n8.x2.trans.shared.b16 {%0,%1}, [%2];\n"
                 : "=r"(r[0]), "=r"(r[1]) : "r"(addr));
}
__device__ __forceinline__ void cp16(uint32_t dst, const void* src){
    asm volatile("cp.async.cg.shared.global [%0], [%1], 16;" :: "r"(dst), "l"(src) : "memory");
}
#define CP_COMMIT() asm volatile("cp.async.commit_group;" ::: "memory")
#define CP_WAIT0()  asm volatile("cp.async.wait_group 0;" ::: "memory")

__device__ __forceinline__ void split_pack(float x, float y, unsigned& hi, unsigned& lo){
    __nv_bfloat16 hx = __float2bfloat16(x);
    __nv_bfloat16 hy = __float2bfloat16(y);
    __nv_bfloat16 lx = __float2bfloat16(x - __bfloat162float(hx));
    __nv_bfloat16 ly = __float2bfloat16(y - __bfloat162float(hy));
    __nv_bfloat162 H; H.x = hx; H.y = hy;
    __nv_bfloat162 Lo; Lo.x = lx; Lo.y = ly;
    hi = *reinterpret_cast<unsigned*>(&H);
    lo = *reinterpret_cast<unsigned*>(&Lo);
}
__device__ __forceinline__ void split_store(__nv_bfloat16* dh, __nv_bfloat16* dl,
                                            int idx, float x, float y){
    unsigned hi, lo; split_pack(x, y, hi, lo);
    *reinterpret_cast<unsigned*>(&dh[idx]) = hi;
    *reinterpret_cast<unsigned*>(&dl[idx]) = lo;
}

// ---------------- conversion kernels ----------------
__global__ __launch_bounds__(256) void cvt_x(const float* __restrict__ x){
    int base = (blockIdx.x*256 + threadIdx.x)*4;
    float4 v = *(const float4*)&x[base];
    split_store(g_xh, g_xl, base,   v.x, v.y);
    split_store(g_xh, g_xl, base+2, v.z, v.w);
}

__global__ __launch_bounds__(256) void cvt_wT(const float* __restrict__ W, int N, int sel){
    __shared__ float tile[32][33];
    int n0 = blockIdx.x*32, k0 = blockIdx.y*32;
    int tx = threadIdx.x & 31, ty = threadIdx.x >> 5;
    __nv_bfloat16* oh = sel ? g_wph : g_wqh;
    __nv_bfloat16* ol = sel ? g_wpl : g_wql;
#pragma unroll
    for (int i = 0; i < 4; i++)
        tile[ty + 8*i][tx] = W[(size_t)(k0 + ty + 8*i)*N + n0 + tx];
    __syncthreads();
#pragma unroll
    for (int i = 0; i < 4; i++){
        int n = n0 + ty + 8*i, k = k0 + tx;
        float v = tile[tx][ty + 8*i];
        __nv_bfloat16 h = __float2bfloat16(v);
        oh[(size_t)n*1024 + k] = h;
        ol[(size_t)n*1024 + k] = __float2bfloat16(v - __bfloat162float(h));
    }
}

__global__ __launch_bounds__(256) void cvt_kv(const float* __restrict__ kc,
                                              const float* __restrict__ vc){
    int base = (blockIdx.x*256 + threadIdx.x)*4;
    int bh = base >> 17;
    int rem = base & (Lq*Eq - 1);
    int s = rem >> 6, e = rem & 63;
    int o = (bh*Sq + s)*Eq + e;
    float4 k4 = *(const float4*)&kc[base];
    float4 v4 = *(const float4*)&vc[base];
    split_store(g_kh, g_kl, o,   k4.x, k4.y);
    split_store(g_kh, g_kl, o+2, k4.z, k4.w);
    split_store(g_vh, g_vl, o,   v4.x, v4.y);
    split_store(g_vh, g_vl, o+2, v4.z, v4.w);
}

// ---------------- split-bf16 MMA GEMM, cp.async double-buffered ------------
// C(M x NDIM) = A(M x 1024) @ B^T + bias.  Block 128m x 128n, 8 warps.
// 2 smem stages x (Ah,Al,Bh,Bl)[128 x 32], stride 40 halves.
#define G_ARR  (128*40)                     // elements per array
#define G_STG  (4*G_ARR)                    // elements per stage
#define GEMM_SMEM (2*G_STG*2)               // bytes = 81920

template<int MODE>
__global__ __launch_bounds__(256) void gemm_mma(const float* __restrict__ bias,
                                               float* __restrict__ out){
    const __nv_bfloat16* Ah = MODE ? g_yh : g_xh;
    const __nv_bfloat16* Al = MODE ? g_yl : g_xl;
    const __nv_bfloat16* Bh = MODE ? g_wph : g_wqh;
    const __nv_bfloat16* Bl = MODE ? g_wpl : g_wql;

    extern __shared__ __align__(16) __nv_bfloat16 dsm[];

    const int t = threadIdx.x, L = t & 31, warp = t >> 5;
    const int wm = warp & 3, wn = warp >> 2;
    const int bm = blockIdx.y*128, bn = blockIdx.x*128;

    float c[2][8][4];
#pragma unroll
    for (int i=0;i<2;i++)
#pragma unroll
        for (int j=0;j<8;j++)
#pragma unroll
            for (int q=0;q<4;q++) c[i][j][q] = 0.f;

    const int lr = t >> 2, lc = t & 3;
    uint32_t sbase = (uint32_t)__cvta_generic_to_shared(dsm);
    uint32_t stg_b[2] = { sbase, sbase + G_STG*2 };

    const int arow = wm*32 + (L & 15);
    const int acol = (L >> 4)*8;
    const int brow = L & 7;
    const int bcol = ((L >> 3) & 1)*8;

    // loader: slab k0 (32-wide) into stage stg
    auto load_slab = [&](int k0, int stg){
        uint32_t sb = stg_b[stg];
#pragma unroll
        for (int hh = 0; hh < 2; hh++){
            int r = lr + hh*64;
            uint32_t d = sb + (uint32_t)((r*40 + lc*8)*2);
            size_t ga = (size_t)(bm + r)*1024 + k0 + lc*8;
            size_t gb = (size_t)(bn + r)*1024 + k0 + lc*8;
            cp16(d,                &Ah[ga]);
            cp16(d + G_ARR*2,      &Al[ga]);
            cp16(d + 2*G_ARR*2,    &Bh[gb]);
            cp16(d + 3*G_ARR*2,    &Bl[gb]);
        }
        CP_COMMIT();
    };

    load_slab(0, 0);

    for (int s = 0; s < 32; s++){
        CP_WAIT0();
        __syncthreads();
        if (s + 1 < 32) load_slab((s+1)*32, (s+1) & 1);

        uint32_t sb = stg_b[s & 1];
        uint32_t sAh = sb, sAl = sb + G_ARR*2, sBh = sb + 2*G_ARR*2, sBl = sb + 3*G_ARR*2;
#pragma unroll
        for (int kk = 0; kk < 2; kk++){
            unsigned ah[2][4], al[2][4];
#pragma unroll
            for (int i=0;i<2;i++){
                unsigned off = (unsigned)(((arow + i*16)*40 + kk*16 + acol)*2);
                ldsm4(ah[i], sAh + off);
                ldsm4(al[i], sAl + off);
            }
#pragma unroll
            for (int j=0;j<8;j++){
                unsigned boff = (unsigned)(((wn*64 + j*8 + brow)*40 + kk*16 + bcol)*2);
                unsigned bhf[2], blf[2];
                ldsm2(bhf, sBh + boff);
                ldsm2(blf, sBl + boff);
#pragma unroll
                for (int i=0;i<2;i++){
                    mma_bf16(c[i][j], ah[i], bhf);
                    mma_bf16(c[i][j], ah[i], blf);
                    mma_bf16(c[i][j], al[i], bhf);
                }
            }
        }
        __syncthreads();
    }

    // epilogue (direct from accumulators)
#pragma unroll
    for (int i=0;i<2;i++){
        int m0 = bm + wm*32 + i*16 + (L >> 2);
#pragma unroll
        for (int j=0;j<8;j++){
            int n = bn + wn*64 + j*8 + 2*(L & 3);
            float b0 = bias[n], b1 = bias[n+1];
            if (MODE == 1){
                float2 r0 = make_float2(c[i][j][0]+b0, c[i][j][1]+b1);
                float2 r1 = make_float2(c[i][j][2]+b0, c[i][j][3]+b1);
                *(float2*)&out[(size_t)m0*1024 + n] = r0;
                *(float2*)&out[(size_t)(m0+8)*1024 + n] = r1;
            } else {
                int third = n >> 10, rem = n & 1023;
                int h = rem >> 6, e = rem & 63;
                float sc = (third == 0) ? 0.125f : 1.0f;
                __nv_bfloat16* dh = (third==0) ? g_qh : (third==1) ? g_kh : g_vh;
                __nv_bfloat16* dl = (third==0) ? g_ql : (third==1) ? g_kl : g_vl;
#pragma unroll
                for (int rr = 0; rr < 2; rr++){
                    int m = m0 + rr*8;
                    int bb = m >> 9, tt = m & 511;
                    int idx = (third==0)
                        ? ((bb*Hq + h)*Tq + tt)*Eq + e
                        : ((bb*Hq + h)*Sq + Lq + tt)*Eq + e;
                    split_store(dh, dl, idx,
                                (c[i][j][2*rr]+b0)*sc, (c[i][j][2*rr+1]+b1)*sc);
                }
            }
        }
    }
}

// ---------------- flash attention, cp.async double-buffered K/V ------------
// Block: 128-query tile for one (b,h). 8 warps. S/P in registers.
// smem: Qh,Ql [128x64] stride 72; 2 stages x (Kh,Kl,Vh,Vl)[64x64] stride 72.
#define A_ARR  (64*72)                      // elements per K/V array
#define A_STG  (4*A_ARR)
#define A_QOFF (2*128*72)                   // elements before stage area
#define ATTN_SMEM ((A_QOFF + 2*A_STG)*2)    // bytes = 110592

__global__ __launch_bounds__(256) void attn_mma(){
    extern __shared__ __align__(16) __nv_bfloat16 sm[];
    __nv_bfloat16* Qh = sm;
    __nv_bfloat16* Ql = sm + 128*72;

    const int qt = blockIdx.x, bh = blockIdx.y;
    const int t = threadIdx.x, L = t & 31, w = t >> 5;

    unsigned sQh = (unsigned)__cvta_generic_to_shared(Qh);
    unsigned sQl = (unsigned)__cvta_generic_to_shared(Ql);
    unsigned sStg[2];
    sStg[0] = (unsigned)__cvta_generic_to_shared(sm + A_QOFF);
    sStg[1] = sStg[0] + A_STG*2;

    // load Q tile (plain; once)
    {
        int r = t >> 1;
        int tok = qt*128 + r;
        size_t gq = ((size_t)bh*Tq + tok)*Eq;
#pragma unroll
        for (int i = 0; i < 4; i++){
            int cchunk = (t & 1)*4 + i;
            *(uint4*)&Qh[r*72 + cchunk*8] = *(const uint4*)&g_qh[gq + cchunk*8];
            *(uint4*)&Ql[r*72 + cchunk*8] = *(const uint4*)&g_ql[gq + cchunk*8];
        }
    }

    float o[8][4];
#pragma unroll
    for (int j=0;j<8;j++)
#pragma unroll
        for (int q=0;q<4;q++) o[j][q] = 0.f;
    float m0_ = -1e30f, m1_ = -1e30f, l0_ = 0.f, l1_ = 0.f;

    const int KT = 34 + 2*qt;
    const int row0 = qt*128 + w*16 + (L >> 2);
    const int lim0 = Lq + row0, lim1 = lim0 + 8;

    const int ldr = t >> 2, ldc = t & 3;
    const size_t kvbase = (size_t)bh*Sq*Eq;

    auto load_tile = [&](int kt, int stg){
        uint32_t sb = sStg[stg];
        size_t gi = kvbase + (size_t)(kt*64 + ldr)*Eq;
#pragma unroll
        for (int hh = 0; hh < 2; hh++){
            int cc = ldc + hh*4;
            uint32_t d = sb + (uint32_t)((ldr*72 + cc*8)*2);
            cp16(d,               &g_kh[gi + cc*8]);
            cp16(d + A_ARR*2,     &g_kl[gi + cc*8]);
            cp16(d + 2*A_ARR*2,   &g_vh[gi + cc*8]);
            cp16(d + 3*A_ARR*2,   &g_vl[gi + cc*8]);
        }
        CP_COMMIT();
    };

    load_tile(0, 0);

    for (int kt = 0; kt < KT; kt++){
        CP_WAIT0();
        __syncthreads();
        if (kt + 1 < KT) load_tile(kt+1, (kt+1) & 1);

        uint32_t sb = sStg[kt & 1];
        uint32_t sKh = sb, sKl = sb + A_ARR*2, sVh = sb + 2*A_ARR*2, sVl = sb + 3*A_ARR*2;

        // ---- S = Q K^T ----
        float s[8][4];
#pragma unroll
        for (int j=0;j<8;j++)
#pragma unroll
            for (int q=0;q<4;q++) s[j][q] = 0.f;

#pragma unroll
        for (int kk = 0; kk < 4; kk++){
            unsigned qa_h[4], qa_l[4];
            unsigned qoff = (unsigned)(((w*16 + (L&15))*72 + kk*16 + (L>>4)*8)*2);
            ldsm4(qa_h, sQh + qoff);
            ldsm4(qa_l, sQl + qoff);
#pragma unroll
            for (int j=0;j<8;j++){
                unsigned koff = (unsigned)(((j*8 + (L&7))*72 + kk*16 + ((L>>3)&1)*8)*2);
                unsigned kb_h[2], kb_l[2];
                ldsm2(kb_h, sKh + koff);
                ldsm2(kb_l, sKl + koff);
                mma_bf16(s[j], qa_h, kb_h);
                mma_bf16(s[j], qa_h, kb_l);
                mma_bf16(s[j], qa_l, kb_h);
            }
        }

        if (kt >= KT-2){
#pragma unroll
            for (int j=0;j<8;j++){
                int col = kt*64 + j*8 + 2*(L & 3);
                if (col   > lim0) s[j][0] = -1e30f;
                if (col+1 > lim0) s[j][1] = -1e30f;
                if (col   > lim1) s[j][2] = -1e30f;
                if (col+1 > lim1) s[j][3] = -1e30f;
            }
        }

        // ---- online softmax ----
        float mt0 = -1e30f, mt1 = -1e30f;
#pragma unroll
        for (int j=0;j<8;j++){
            mt0 = fmaxf(mt0, fmaxf(s[j][0], s[j][1]));
            mt1 = fmaxf(mt1, fmaxf(s[j][2], s[j][3]));
        }
        mt0 = fmaxf(mt0, __shfl_xor_sync(0xffffffffu, mt0, 1));
        mt0 = fmaxf(mt0, __shfl_xor_sync(0xffffffffu, mt0, 2));
        mt1 = fmaxf(mt1, __shfl_xor_sync(0xffffffffu, mt1, 1));
        mt1 = fmaxf(mt1, __shfl_xor_sync(0xffffffffu, mt1, 2));

        float nm0 = fmaxf(m0_, mt0), nm1 = fmaxf(m1_, mt1);
        float corr0 = __expf(m0_ - nm0), corr1 = __expf(m1_ - nm1);
        m0_ = nm0; m1_ = nm1;
        l0_ *= corr0; l1_ *= corr1;
#pragma unroll
        for (int j=0;j<8;j++){
            o[j][0] *= corr0; o[j][1] *= corr0;
            o[j][2] *= corr1; o[j][3] *= corr1;
        }
        float rs0 = 0.f, rs1 = 0.f;
#pragma unroll
        for (int j=0;j<8;j++){
            s[j][0] = __expf(s[j][0] - nm0); rs0 += s[j][0];
            s[j][1] = __expf(s[j][1] - nm0); rs0 += s[j][1];
            s[j][2] = __expf(s[j][2] - nm1); rs1 += s[j][2];
            s[j][3] = __expf(s[j][3] - nm1); rs1 += s[j][3];
        }
        rs0 += __shfl_xor_sync(0xffffffffu, rs0, 1);
        rs0 += __shfl_xor_sync(0xffffffffu, rs0, 2);
        rs1 += __shfl_xor_sync(0xffffffffu, rs1, 1);
        rs1 += __shfl_xor_sync(0xffffffffu, rs1, 2);
        l0_ += rs0; l1_ += rs1;

        // ---- O += P V ----
#pragma unroll
        for (int kk2 = 0; kk2 < 4; kk2++){
            unsigned pa_h[4], pa_l[4];
            split_pack(s[2*kk2][0],   s[2*kk2][1],   pa_h[0], pa_l[0]);
            split_pack(s[2*kk2][2],   s[2*kk2][3],   pa_h[1], pa_l[1]);
            split_pack(s[2*kk2+1][0], s[2*kk2+1][1], pa_h[2], pa_l[2]);
            split_pack(s[2*kk2+1][2], s[2*kk2+1][3], pa_h[3], pa_l[3]);
#pragma unroll
            for (int j=0;j<8;j++){
                unsigned voff = (unsigned)(((kk2*16 + (L&15))*72 + j*8)*2);
                unsigned vb_h[2], vb_l[2];
                ldsm2t(vb_h, sVh + voff);
                ldsm2t(vb_l, sVl + voff);
                mma_bf16(o[j], pa_h, vb_h);
                mma_bf16(o[j], pa_h, vb_l);
                mma_bf16(o[j], pa_l, vb_h);
            }
        }
        __syncthreads();
    }

    // ---- finalize -> split y ----
    float inv0 = 1.0f / l0_, inv1 = 1.0f / l1_;
    int b_ = bh >> 4, h = bh & 15;
    int tok0 = qt*128 + w*16 + (L >> 2);
#pragma unroll
    for (int j=0;j<8;j++){
        int cc = h*Eq + j*8 + 2*(L & 3);
        int i0 = (b_*Tq + tok0)*Cq + cc;
        int i1 = (b_*Tq + tok0 + 8)*Cq + cc;
        split_store(g_yh, g_yl, i0, o[j][0]*inv0, o[j][1]*inv0);
        split_store(g_yh, g_yl, i1, o[j][2]*inv1, o[j][3]*inv1);
    }
}

// ---------------------------------------------------------------------------
extern "C" void kernel_launch(void* const* d_in, const int* in_sizes, int n_in,
                              void* d_out, int out_size)
{
    const float* x     = (const float*)d_in[0];
    const float* kc    = (const float*)d_in[1];
    const float* vc    = (const float*)d_in[2];
    const float* Wqkv  = (const float*)d_in[3];
    const float* bqkv  = (const float*)d_in[4];
    const float* Wproj = (const float*)d_in[5];
    const float* bproj = (const float*)d_in[6];
    float* out = (float*)d_out;

    cudaFuncSetAttribute(attn_mma,
                         cudaFuncAttributeMaxDynamicSharedMemorySize, ATTN_SMEM);
    cudaFuncSetAttribute(gemm_mma<0>,
                         cudaFuncAttributeMaxDynamicSharedMemorySize, GEMM_SMEM);
    cudaFuncSetAttribute(gemm_mma<1>,
                         cudaFuncAttributeMaxDynamicSharedMemorySize, GEMM_SMEM);

    // conversions
    cvt_x<<<4096, 256>>>(x);
    cvt_wT<<<dim3(96, 32), 256>>>(Wqkv, 3072, 0);
    cvt_wT<<<dim3(32, 32), 256>>>(Wproj, 1024, 1);
    cvt_kv<<<16384, 256>>>(kc, vc);

    // QKV projection -> split q/k/v caches
    gemm_mma<0><<<dim3(24, 32), 256, GEMM_SMEM>>>(bqkv, nullptr);

    // attention -> split y
    attn_mma<<<dim3(4, 128), 256, ATTN_SMEM>>>();

    // output projection -> d_out (f32)
    gemm_mma<1><<<dim3(8, 32), 256, GEMM_SMEM>>>(bproj, out);
}

// round 9
// speedup vs baseline: 2.7216x; 1.0259x over previous
#include <cuda_runtime.h>
#include <cuda_bf16.h>
#include <cstdint>

#define Bq 8
#define Tq 512
#define Cq 1024
#define Hq 16
#define Eq 64
#define Lq 2048
#define Sq 2560   // L + T

// ---------------- split-bf16 scratch (device globals) ----------------
__device__ __align__(16) __nv_bfloat16 g_xh[4096*1024], g_xl[4096*1024];
__device__ __align__(16) __nv_bfloat16 g_wqh[3072*1024], g_wql[3072*1024];  // Wqkv^T (n,k)
__device__ __align__(16) __nv_bfloat16 g_wph[1024*1024], g_wpl[1024*1024];  // Wproj^T
__device__ __align__(16) __nv_bfloat16 g_qh[Bq*Hq*Tq*Eq], g_ql[Bq*Hq*Tq*Eq];
__device__ __align__(16) __nv_bfloat16 g_kh[Bq*Hq*Sq*Eq], g_kl[Bq*Hq*Sq*Eq];
__device__ __align__(16) __nv_bfloat16 g_vh[Bq*Hq*Sq*Eq], g_vl[Bq*Hq*Sq*Eq];
__device__ __align__(16) __nv_bfloat16 g_yh[4096*1024], g_yl[4096*1024];

// ---------------- PTX helpers ----------------
__device__ __forceinline__ void mma_bf16(float* c, const unsigned* a, const unsigned* b){
    asm volatile(
        "mma.sync.aligned.m16n8k16.row.col.f32.bf16.bf16.f32 "
        "{%0,%1,%2,%3}, {%4,%5,%6,%7}, {%8,%9}, {%0,%1,%2,%3};\n"
        : "+f"(c[0]), "+f"(c[1]), "+f"(c[2]), "+f"(c[3])
        : "r"(a[0]), "r"(a[1]), "r"(a[2]), "r"(a[3]), "r"(b[0]), "r"(b[1]));
}
__device__ __forceinline__ void ldsm4(unsigned* r, unsigned addr){
    asm volatile("ldmatrix.sync.aligned.m8n8.x4.shared.b16 {%0,%1,%2,%3}, [%4];\n"
                 : "=r"(r[0]), "=r"(r[1]), "=r"(r[2]), "=r"(r[3]) : "r"(addr));
}
__device__ __forceinline__ void ldsm2(unsigned* r, unsigned addr){
    asm volatile("ldmatrix.sync.aligned.m8n8.x2.shared.b16 {%0,%1}, [%2];\n"
                 : "=r"(r[0]), "=r"(r[1]) : "r"(addr));
}
__device__ __forceinline__ void ldsm2t(unsigned* r, unsigned addr){
    asm volatile("ldmatrix.sync.aligned.m8n8.x2.trans.shared.b16 {%0,%1}, [%2];\n"
                 : "=r"(r[0]), "=r"(r[1]) : "r"(addr));
}
__device__ __forceinline__ void cp16(uint32_t dst, const void* src){
    asm volatile("cp.async.cg.shared.global [%0], [%1], 16;" :: "r"(dst), "l"(src) : "memory");
}
#define CP_COMMIT() asm volatile("cp.async.commit_group;" ::: "memory")
#define CP_WAIT0()  asm volatile("cp.async.wait_group 0;" ::: "memory")

__device__ __forceinline__ void split_pack(float x, float y, unsigned& hi, unsigned& lo){
    __nv_bfloat16 hx = __float2bfloat16(x);
    __nv_bfloat16 hy = __float2bfloat16(y);
    __nv_bfloat16 lx = __float2bfloat16(x - __bfloat162float(hx));
    __nv_bfloat16 ly = __float2bfloat16(y - __bfloat162float(hy));
    __nv_bfloat162 H; H.x = hx; H.y = hy;
    __nv_bfloat162 Lo; Lo.x = lx; Lo.y = ly;
    hi = *reinterpret_cast<unsigned*>(&H);
    lo = *reinterpret_cast<unsigned*>(&Lo);
}
__device__ __forceinline__ void split_store(__nv_bfloat16* dh, __nv_bfloat16* dl,
                                            int idx, float x, float y){
    unsigned hi, lo; split_pack(x, y, hi, lo);
    *reinterpret_cast<unsigned*>(&dh[idx]) = hi;
    *reinterpret_cast<unsigned*>(&dl[idx]) = lo;
}

// ---------------- conversion bodies ----------------
__device__ __forceinline__ void wT_tile_body(const float* __restrict__ W, int N,
                                             __nv_bfloat16* oh, __nv_bfloat16* ol,
                                             int n0, int k0, float* tile /*32x33*/){
    int tx = threadIdx.x & 31, ty = threadIdx.x >> 5;
#pragma unroll
    for (int i = 0; i < 4; i++)
        tile[(ty + 8*i)*33 + tx] = W[(size_t)(k0 + ty + 8*i)*N + n0 + tx];
    __syncthreads();
#pragma unroll
    for (int i = 0; i < 4; i++){
        int n = n0 + ty + 8*i, k = k0 + tx;
        float v = tile[tx*33 + ty + 8*i];
        __nv_bfloat16 h = __float2bfloat16(v);
        oh[(size_t)n*1024 + k] = h;
        ol[(size_t)n*1024 + k] = __float2bfloat16(v - __bfloat162float(h));
    }
    __syncthreads();
}

// Pre-kernel: x split + Wqkv^T split (all predecessors of the QKV GEMM)
__global__ __launch_bounds__(256) void cvt_pre(const float* __restrict__ x,
                                               const float* __restrict__ Wqkv){
    __shared__ float tile[32*33];
    int bid = blockIdx.x;
    if (bid < 4096){
        int base = (bid*256 + threadIdx.x)*4;
        float4 v = *(const float4*)&x[base];
        split_store(g_xh, g_xl, base,   v.x, v.y);
        split_store(g_xh, g_xl, base+2, v.z, v.w);
    } else {
        int id = bid - 4096;                    // 0..3071
        int n0 = (id % 96)*32, k0 = (id / 96)*32;
        wT_tile_body(Wqkv, 3072, g_wqh, g_wql, n0, k0, tile);
    }
}

// ---------------- GEMM sizes ----------------
#define G_ARR  (128*40)
#define G_STG  (4*G_ARR)
#define GEMM_SMEM (2*G_STG*2)               // 81920 B

// Shared GEMM mainloop + epilogue (MODE 0 = qkv scatter, 1 = f32 out)
template<int MODE>
__device__ __forceinline__ void gemm_body(int bm, int bn,
                                          const float* __restrict__ bias,
                                          float* __restrict__ out,
                                          __nv_bfloat16* dsm){
    const __nv_bfloat16* Ah = MODE ? g_yh : g_xh;
    const __nv_bfloat16* Al = MODE ? g_yl : g_xl;
    const __nv_bfloat16* Bh = MODE ? g_wph : g_wqh;
    const __nv_bfloat16* Bl = MODE ? g_wpl : g_wql;

    const int t = threadIdx.x, L = t & 31, warp = t >> 5;
    const int wm = warp & 3, wn = warp >> 2;

    float c[2][8][4];
#pragma unroll
    for (int i=0;i<2;i++)
#pragma unroll
        for (int j=0;j<8;j++)
#pragma unroll
            for (int q=0;q<4;q++) c[i][j][q] = 0.f;

    const int lr = t >> 2, lc = t & 3;
    uint32_t sbase = (uint32_t)__cvta_generic_to_shared(dsm);
    uint32_t stg_b[2] = { sbase, sbase + G_STG*2 };

    const int arow = wm*32 + (L & 15);
    const int acol = (L >> 4)*8;
    const int brow = L & 7;
    const int bcol = ((L >> 3) & 1)*8;

    auto load_slab = [&](int k0, int stg){
        uint32_t sb = stg_b[stg];
#pragma unroll
        for (int hh = 0; hh < 2; hh++){
            int r = lr + hh*64;
            uint32_t d = sb + (uint32_t)((r*40 + lc*8)*2);
            size_t ga = (size_t)(bm + r)*1024 + k0 + lc*8;
            size_t gb = (size_t)(bn + r)*1024 + k0 + lc*8;
            cp16(d,                &Ah[ga]);
            cp16(d + G_ARR*2,      &Al[ga]);
            cp16(d + 2*G_ARR*2,    &Bh[gb]);
            cp16(d + 3*G_ARR*2,    &Bl[gb]);
        }
        CP_COMMIT();
    };

    load_slab(0, 0);

    for (int s = 0; s < 32; s++){
        CP_WAIT0();
        __syncthreads();
        if (s + 1 < 32) load_slab((s+1)*32, (s+1) & 1);

        uint32_t sb = stg_b[s & 1];
        uint32_t sAh = sb, sAl = sb + G_ARR*2, sBh = sb + 2*G_ARR*2, sBl = sb + 3*G_ARR*2;
#pragma unroll
        for (int kk = 0; kk < 2; kk++){
            unsigned ah[2][4], al[2][4];
#pragma unroll
            for (int i=0;i<2;i++){
                unsigned off = (unsigned)(((arow + i*16)*40 + kk*16 + acol)*2);
                ldsm4(ah[i], sAh + off);
                ldsm4(al[i], sAl + off);
            }
#pragma unroll
            for (int j=0;j<8;j++){
                unsigned boff = (unsigned)(((wn*64 + j*8 + brow)*40 + kk*16 + bcol)*2);
                unsigned bhf[2], blf[2];
                ldsm2(bhf, sBh + boff);
                ldsm2(blf, sBl + boff);
#pragma unroll
                for (int i=0;i<2;i++){
                    mma_bf16(c[i][j], ah[i], bhf);
                    mma_bf16(c[i][j], ah[i], blf);
                    mma_bf16(c[i][j], al[i], bhf);
                }
            }
        }
        __syncthreads();
    }

#pragma unroll
    for (int i=0;i<2;i++){
        int m0 = bm + wm*32 + i*16 + (L >> 2);
#pragma unroll
        for (int j=0;j<8;j++){
            int n = bn + wn*64 + j*8 + 2*(L & 3);
            float b0 = bias[n], b1 = bias[n+1];
            if (MODE == 1){
                float2 r0 = make_float2(c[i][j][0]+b0, c[i][j][1]+b1);
                float2 r1 = make_float2(c[i][j][2]+b0, c[i][j][3]+b1);
                *(float2*)&out[(size_t)m0*1024 + n] = r0;
                *(float2*)&out[(size_t)(m0+8)*1024 + n] = r1;
            } else {
                int third = n >> 10, rem = n & 1023;
                int h = rem >> 6, e = rem & 63;
                float sc = (third == 0) ? 0.125f : 1.0f;
                __nv_bfloat16* dh = (third==0) ? g_qh : (third==1) ? g_kh : g_vh;
                __nv_bfloat16* dl = (third==0) ? g_ql : (third==1) ? g_kl : g_vl;
#pragma unroll
                for (int rr = 0; rr < 2; rr++){
                    int m = m0 + rr*8;
                    int bb = m >> 9, tt = m & 511;
                    int idx = (third==0)
                        ? ((bb*Hq + h)*Tq + tt)*Eq + e
                        : ((bb*Hq + h)*Sq + Lq + tt)*Eq + e;
                    split_store(dh, dl, idx,
                                (c[i][j][2*rr]+b0)*sc, (c[i][j][2*rr+1]+b1)*sc);
                }
            }
        }
    }
}

// Fused launch: blocks 0..511 convert K/V cache, 512..767 convert Wproj^T,
// 768..1535 run the QKV GEMM tiles. Conversions are DRAM-bound and
// independent of the GEMM, so they overlap its tensor-bound waves.
__global__ __launch_bounds__(256) void gemm0_fused(const float* __restrict__ bias,
                                                   const float* __restrict__ kc,
                                                   const float* __restrict__ vc,
                                                   const float* __restrict__ Wproj){
    extern __shared__ __align__(16) __nv_bfloat16 dsm[];
    const int bid = blockIdx.x;

    if (bid < 512){
        // K/V cache split: 512 blocks x 32 grid-stride chunks = 16384 chunks
#pragma unroll 4
        for (int it = 0; it < 32; it++){
            int base = ((bid + it*512)*256 + threadIdx.x)*4;
            int bh = base >> 17;
            int rem = base & (Lq*Eq - 1);
            int s = rem >> 6, e = rem & 63;
            int o = (bh*Sq + s)*Eq + e;
            float4 k4 = *(const float4*)&kc[base];
            float4 v4 = *(const float4*)&vc[base];
            split_store(g_kh, g_kl, o,   k4.x, k4.y);
            split_store(g_kh, g_kl, o+2, k4.z, k4.w);
            split_store(g_vh, g_vl, o,   v4.x, v4.y);
            split_store(g_vh, g_vl, o+2, v4.z, v4.w);
        }
        return;
    }
    if (bid < 768){
        // Wproj^T split: 256 blocks x 4 tiles (32x32 grid of 32x32 tiles)
        float* tile = (float*)dsm;
        int id = bid - 512;
#pragma unroll
        for (int it = 0; it < 4; it++){
            int tl = id + it*256;                // 0..1023
            int n0 = (tl & 31)*32, k0 = (tl >> 5)*32;
            wT_tile_body(Wproj, 1024, g_wph, g_wpl, n0, k0, tile);
        }
        return;
    }
    // QKV GEMM tile
    int g = bid - 768;                            // 0..767
    gemm_body<0>((g / 24)*128, (g % 24)*128, bias, nullptr, dsm);
}

template<int MODE>
__global__ __launch_bounds__(256) void gemm_mma(const float* __restrict__ bias,
                                               float* __restrict__ out){
    extern __shared__ __align__(16) __nv_bfloat16 dsm[];
    gemm_body<MODE>(blockIdx.y*128, blockIdx.x*128, bias, out, dsm);
}

// ---------------- flash attention, cp.async double-buffered K/V ------------
// 1-D grid, longest blocks (qt=3) first: qt = 3 - bx/128, bh = bx%128.
#define A_ARR  (64*72)
#define A_STG  (4*A_ARR)
#define A_QOFF (2*128*72)
#define ATTN_SMEM ((A_QOFF + 2*A_STG)*2)    // 110592 B

__global__ __launch_bounds__(256) void attn_mma(){
    extern __shared__ __align__(16) __nv_bfloat16 sm[];
    __nv_bfloat16* Qh = sm;
    __nv_bfloat16* Ql = sm + 128*72;

    const int bx = blockIdx.x;
    const int qt = 3 - (bx >> 7);          // longest-first
    const int bh = bx & 127;
    const int t = threadIdx.x, L = t & 31, w = t >> 5;

    unsigned sQh = (unsigned)__cvta_generic_to_shared(Qh);
    unsigned sQl = (unsigned)__cvta_generic_to_shared(Ql);
    unsigned sStg[2];
    sStg[0] = (unsigned)__cvta_generic_to_shared(sm + A_QOFF);
    sStg[1] = sStg[0] + A_STG*2;

    {
        int r = t >> 1;
        int tok = qt*128 + r;
        size_t gq = ((size_t)bh*Tq + tok)*Eq;
#pragma unroll
        for (int i = 0; i < 4; i++){
            int cchunk = (t & 1)*4 + i;
            *(uint4*)&Qh[r*72 + cchunk*8] = *(const uint4*)&g_qh[gq + cchunk*8];
            *(uint4*)&Ql[r*72 + cchunk*8] = *(const uint4*)&g_ql[gq + cchunk*8];
        }
    }

    float o[8][4];
#pragma unroll
    for (int j=0;j<8;j++)
#pragma unroll
        for (int q=0;q<4;q++) o[j][q] = 0.f;
    float m0_ = -1e30f, m1_ = -1e30f, l0_ = 0.f, l1_ = 0.f;

    const int KT = 34 + 2*qt;
    const int row0 = qt*128 + w*16 + (L >> 2);
    const int lim0 = Lq + row0, lim1 = lim0 + 8;

    const int ldr = t >> 2, ldc = t & 3;
    const size_t kvbase = (size_t)bh*Sq*Eq;

    auto load_tile = [&](int kt, int stg){
        uint32_t sb = sStg[stg];
        size_t gi = kvbase + (size_t)(kt*64 + ldr)*Eq;
#pragma unroll
        for (int hh = 0; hh < 2; hh++){
            int cc = ldc + hh*4;
            uint32_t d = sb + (uint32_t)((ldr*72 + cc*8)*2);
            cp16(d,               &g_kh[gi + cc*8]);
            cp16(d + A_ARR*2,     &g_kl[gi + cc*8]);
            cp16(d + 2*A_ARR*2,   &g_vh[gi + cc*8]);
            cp16(d + 3*A_ARR*2,   &g_vl[gi + cc*8]);
        }
        CP_COMMIT();
    };

    load_tile(0, 0);

    for (int kt = 0; kt < KT; kt++){
        CP_WAIT0();
        __syncthreads();
        if (kt + 1 < KT) load_tile(kt+1, (kt+1) & 1);

        uint32_t sb = sStg[kt & 1];
        uint32_t sKh = sb, sKl = sb + A_ARR*2, sVh = sb + 2*A_ARR*2, sVl = sb + 3*A_ARR*2;

        float s[8][4];
#pragma unroll
        for (int j=0;j<8;j++)
#pragma unroll
            for (int q=0;q<4;q++) s[j][q] = 0.f;

#pragma unroll
        for (int kk = 0; kk < 4; kk++){
            unsigned qa_h[4], qa_l[4];
            unsigned qoff = (unsigned)(((w*16 + (L&15))*72 + kk*16 + (L>>4)*8)*2);
            ldsm4(qa_h, sQh + qoff);
            ldsm4(qa_l, sQl + qoff);
#pragma unroll
            for (int j=0;j<8;j++){
                unsigned koff = (unsigned)(((j*8 + (L&7))*72 + kk*16 + ((L>>3)&1)*8)*2);
                unsigned kb_h[2], kb_l[2];
                ldsm2(kb_h, sKh + koff);
                ldsm2(kb_l, sKl + koff);
                mma_bf16(s[j], qa_h, kb_h);
                mma_bf16(s[j], qa_h, kb_l);
                mma_bf16(s[j], qa_l, kb_h);
            }
        }

        if (kt >= KT-2){
#pragma unroll
            for (int j=0;j<8;j++){
                int col = kt*64 + j*8 + 2*(L & 3);
                if (col   > lim0) s[j][0] = -1e30f;
                if (col+1 > lim0) s[j][1] = -1e30f;
                if (col   > lim1) s[j][2] = -1e30f;
                if (col+1 > lim1) s[j][3] = -1e30f;
            }
        }

        float mt0 = -1e30f, mt1 = -1e30f;
#pragma unroll
        for (int j=0;j<8;j++){
            mt0 = fmaxf(mt0, fmaxf(s[j][0], s[j][1]));
            mt1 = fmaxf(mt1, fmaxf(s[j][2], s[j][3]));
        }
        mt0 = fmaxf(mt0, __shfl_xor_sync(0xffffffffu, mt0, 1));
        mt0 = fmaxf(mt0, __shfl_xor_sync(0xffffffffu, mt0, 2));
        mt1 = fmaxf(mt1, __shfl_xor_sync(0xffffffffu, mt1, 1));
        mt1 = fmaxf(mt1, __shfl_xor_sync(0xffffffffu, mt1, 2));

        float nm0 = fmaxf(m0_, mt0), nm1 = fmaxf(m1_, mt1);
        float corr0 = __expf(m0_ - nm0), corr1 = __expf(m1_ - nm1);
        m0_ = nm0; m1_ = nm1;
        l0_ *= corr0; l1_ *= corr1;
#pragma unroll
        for (int j=0;j<8;j++){
            o[j][0] *= corr0; o[j][1] *= corr0;
            o[j][2] *= corr1; o[j][3] *= corr1;
        }
        float rs0 = 0.f, rs1 = 0.f;
#pragma unroll
        for (int j=0;j<8;j++){
            s[j][0] = __expf(s[j][0] - nm0); rs0 += s[j][0];
            s[j][1] = __expf(s[j][1] - nm0); rs0 += s[j][1];
            s[j][2] = __expf(s[j][2] - nm1); rs1 += s[j][2];
            s[j][3] = __expf(s[j][3] - nm1); rs1 += s[j][3];
        }
        rs0 += __shfl_xor_sync(0xffffffffu, rs0, 1);
        rs0 += __shfl_xor_sync(0xffffffffu, rs0, 2);
        rs1 += __shfl_xor_sync(0xffffffffu, rs1, 1);
        rs1 += __shfl_xor_sync(0xffffffffu, rs1, 2);
        l0_ += rs0; l1_ += rs1;

#pragma unroll
        for (int kk2 = 0; kk2 < 4; kk2++){
            unsigned pa_h[4], pa_l[4];
            split_pack(s[2*kk2][0],   s[2*kk2][1],   pa_h[0], pa_l[0]);
            split_pack(s[2*kk2][2],   s[2*kk2][3],   pa_h[1], pa_l[1]);
            split_pack(s[2*kk2+1][0], s[2*kk2+1][1], pa_h[2], pa_l[2]);
            split_pack(s[2*kk2+1][2], s[2*kk2+1][3], pa_h[3], pa_l[3]);
#pragma unroll
            for (int j=0;j<8;j++){
                unsigned voff = (unsigned)(((kk2*16 + (L&15))*72 + j*8)*2);
                unsigned vb_h[2], vb_l[2];
                ldsm2t(vb_h, sVh + voff);
                ldsm2t(vb_l, sVl + voff);
                mma_bf16(o[j], pa_h, vb_h);
                mma_bf16(o[j], pa_h, vb_l);
                mma_bf16(o[j], pa_l, vb_h);
            }
        }
        __syncthreads();
    }

    float inv0 = 1.0f / l0_, inv1 = 1.0f / l1_;
    int b_ = bh >> 4, h = bh & 15;
    int tok0 = qt*128 + w*16 + (L >> 2);
#pragma unroll
    for (int j=0;j<8;j++){
        int cc = h*Eq + j*8 + 2*(L & 3);
        int i0 = (b_*Tq + tok0)*Cq + cc;
        int i1 = (b_*Tq + tok0 + 8)*Cq + cc;
        split_store(g_yh, g_yl, i0, o[j][0]*inv0, o[j][1]*inv0);
        split_store(g_yh, g_yl, i1, o[j][2]*inv1, o[j][3]*inv1);
    }
}

// ---------------------------------------------------------------------------
extern "C" void kernel_launch(void* const* d_in, const int* in_sizes, int n_in,
                              void* d_out, int out_size)
{
    const float* x     = (const float*)d_in[0];
    const float* kc    = (const float*)d_in[1];
    const float* vc    = (const float*)d_in[2];
    const float* Wqkv  = (const float*)d_in[3];
    const float* bqkv  = (const float*)d_in[4];
    const float* Wproj = (const float*)d_in[5];
    const float* bproj = (const float*)d_in[6];
    float* out = (float*)d_out;

    cudaFuncSetAttribute(attn_mma,
                         cudaFuncAttributeMaxDynamicSharedMemorySize, ATTN_SMEM);
    cudaFuncSetAttribute(gemm0_fused,
                         cudaFuncAttributeMaxDynamicSharedMemorySize, GEMM_SMEM);
    cudaFuncSetAttribute(gemm_mma<1>,
                         cudaFuncAttributeMaxDynamicSharedMemorySize, GEMM_SMEM);

    // 1) x + Wqkv^T conversions (predecessors of the QKV GEMM)
    cvt_pre<<<7168, 256>>>(x, Wqkv);

    // 2) QKV GEMM fused with K/V-cache + Wproj^T conversions (overlap on idle DRAM)
    gemm0_fused<<<1536, 256, GEMM_SMEM>>>(bqkv, kc, vc, Wproj);

    // 3) attention -> split y (longest blocks first)
    attn_mma<<<512, 256, ATTN_SMEM>>>();

    // 4) output projection -> d_out (f32)
    gemm_mma<1><<<dim3(8, 32), 256, GEMM_SMEM>>>(bproj, out);
}